// round 7
// baseline (speedup 1.0000x reference)
#include <cuda_runtime.h>
#include <math.h>

// AFNO2D: rfft2(ortho) -> blockwise complex MLP (GELU, softshrink) -> irfft2(ortho)
// x[4,128,128,768] fp32. All scratch in __device__ globals (no allocation).

#define BB 4
#define HH 128
#define WW 128
#define CC 768
#define NB 8
#define BSZ 96
#define WF 65            // W half-spectrum size
#define NPOS (BB*WF*HH)  // 33280 frequency positions

// Scratch buffers. Layout for A/B: [b][kw(0..64)][h or kh (0..127)][c(0..767)]
// A: stage1 out -> stage2 in/out (in-place) -> MLP1 in ; MLP2 out -> invH in/out -> invW in
// B: MLP1 out -> MLP2 in
__device__ float g_AR[BB*WF*HH*CC];
__device__ float g_AI[BB*WF*HH*CC];
__device__ float g_BR[BB*WF*HH*CC];
__device__ float g_BI[BB*WF*HH*CC];

// ---------------------------------------------------------------------------
// Shared-memory cooperative 128-point complex FFT.
// Block = 1024 threads = 32 channel lanes x 32 butterfly-thread groups.
// Data layout in smem: s[w*32 + c]  (warp = 32 consecutive c -> conflict-free)
// DIT with bit-reversed input load; 64 butterflies/stage, 2 per thread.
// ---------------------------------------------------------------------------

__device__ __forceinline__ void build_tw(float* twc, float* tws, int tid, float sign) {
    // Twiddle table: for stage with `half`, k in [0,half): index (half-1)+k,
    // angle = sign * pi * k / half = sign * 2*pi*k/len.  127 entries total.
    if (tid < 127) {
        int half = 1 << (31 - __clz(tid + 1));
        int k = tid + 1 - half;
        float ang = sign * 3.14159265358979323846f * (float)k / (float)half;
        twc[tid] = cosf(ang);
        tws[tid] = sinf(ang);
    }
}

__device__ __forceinline__ void fft128(float* sr, float* si,
                                       const float* twc, const float* tws, int tid) {
    const int c  = tid & 31;
    const int jt = tid >> 5;
    int s = 0;
    for (int half = 1; half < 128; half <<= 1, s++) {
        #pragma unroll
        for (int q = 0; q < 2; q++) {
            int j  = jt + (q << 5);             // butterfly index 0..63 (disjoint pairs)
            int k  = j & (half - 1);
            int i0 = ((j >> s) << (s + 1)) + k;
            int i1 = i0 + half;
            float twr = twc[half - 1 + k];
            float twi = tws[half - 1 + k];
            float ar = sr[i1*32 + c], ai = si[i1*32 + c];
            float vr = ar*twr - ai*twi;
            float vi = ar*twi + ai*twr;
            float ur = sr[i0*32 + c], ui = si[i0*32 + c];
            sr[i0*32 + c] = ur + vr;  si[i0*32 + c] = ui + vi;
            sr[i1*32 + c] = ur - vr;  si[i1*32 + c] = ui - vi;
        }
        __syncthreads();
    }
}

// ---- Stage 1: real FFT along W.  x[b,h,w,c] -> A[b][kw][h][c], kw=0..64 ----
__global__ __launch_bounds__(1024) void k_wfft(const float* __restrict__ x) {
    __shared__ float sr[4096], si[4096], twc[128], tws[128];
    const int tid = threadIdx.x;
    const int c0  = blockIdx.x * 32;
    const int h   = blockIdx.y;
    const int b   = blockIdx.z;
    build_tw(twc, tws, tid, -1.0f);
    const float* src = x + ((b*HH + h)*WW)*CC + c0;
    for (int idx = tid; idx < 4096; idx += 1024) {
        int w = idx >> 5, c = idx & 31;
        int r = __brev(w) >> 25;
        sr[r*32 + c] = src[w*CC + c];
        si[r*32 + c] = 0.0f;
    }
    __syncthreads();
    fft128(sr, si, twc, tws, tid);
    float* dR = g_AR + ((b*WF)*HH + h)*CC + c0;
    float* dI = g_AI + ((b*WF)*HH + h)*CC + c0;
    for (int idx = tid; idx < 65*32; idx += 1024) {
        int k = idx >> 5, c = idx & 31;
        int off = k*(HH*CC) + c;
        dR[off] = sr[k*32 + c];
        dI[off] = si[k*32 + c];
    }
}

// ---- Stage 2 / inverse stage: complex FFT along H axis, in-place on A ----
// SIGN=-1 forward (with ortho 1/128 scale), SIGN=+1 inverse (no scale).
template<int SIGN, bool SCALE>
__global__ __launch_bounds__(1024) void k_hfft() {
    __shared__ float sr[4096], si[4096], twc[128], tws[128];
    const int tid = threadIdx.x;
    const int c0  = blockIdx.x * 32;
    const int kw  = blockIdx.y;
    const int b   = blockIdx.z;
    build_tw(twc, tws, tid, (float)SIGN);
    float* pR = g_AR + ((b*WF + kw)*HH)*CC + c0;
    float* pI = g_AI + ((b*WF + kw)*HH)*CC + c0;
    for (int idx = tid; idx < 4096; idx += 1024) {
        int hh = idx >> 5, c = idx & 31;
        int r = __brev(hh) >> 25;
        sr[r*32 + c] = pR[hh*CC + c];
        si[r*32 + c] = pI[hh*CC + c];
    }
    __syncthreads();
    fft128(sr, si, twc, tws, tid);
    const float sc = SCALE ? 0.0078125f : 1.0f;
    for (int idx = tid; idx < 4096; idx += 1024) {
        int kh = idx >> 5, c = idx & 31;
        pR[kh*CC + c] = sr[kh*32 + c] * sc;
        pI[kh*CC + c] = si[kh*32 + c] * sc;
    }
}

// ---- Final stage: inverse real FFT along W (Hermitian mirror), write out ----
__global__ __launch_bounds__(1024) void k_iwfft(float* __restrict__ out) {
    __shared__ float sr[4096], si[4096], twc[128], tws[128];
    const int tid = threadIdx.x;
    const int c0  = blockIdx.x * 32;
    const int h   = blockIdx.y;
    const int b   = blockIdx.z;
    build_tw(twc, tws, tid, 1.0f);
    for (int idx = tid; idx < 4096; idx += 1024) {
        int kk = idx >> 5, c = idx & 31;
        int kp = (kk <= 64) ? kk : (128 - kk);
        int addr = ((b*WF + kp)*HH + h)*CC + c0 + c;
        float vr = g_AR[addr];
        float vi = g_AI[addr];
        if (kk > 64) vi = -vi;     // conjugate mirror
        int r = __brev(kk) >> 25;
        sr[r*32 + c] = vr;
        si[r*32 + c] = vi;
    }
    __syncthreads();
    fft128(sr, si, twc, tws, tid);
    float* dst = out + ((b*HH + h)*WW)*CC + c0;
    for (int idx = tid; idx < 4096; idx += 1024) {
        int w = idx >> 5, c = idx & 31;
        dst[w*CC + c] = sr[w*32 + c] * 0.0078125f;  // inverse ortho 1/128, real part
    }
}

// ---------------------------------------------------------------------------
// Block-diagonal complex MLP layers.
// Layer 1: O = GELU( Xr@Wr - Xi@Wi + br ,  Xi@Wr + Xr@Wi + bi )   A -> B
// Layer 2: same matmul form, then softshrink(0.01)                B -> A
// CTA: 128 positions x one channel block (96). 384 threads, 8x4 complex tile.
// ---------------------------------------------------------------------------

#define MT  128
#define SXP 100   // padded row pitch for x tiles (keeps float4 store alignment)
#define MLP_SMEM_FLOATS (9216*2 + MT*SXP*2 + 96*2)
#define MLP_SMEM_BYTES  (MLP_SMEM_FLOATS * 4)

__device__ __forceinline__ float gelu_exact(float v) {
    return 0.5f * v * (1.0f + erff(v * 0.70710678118654752f));
}
__device__ __forceinline__ float sshrink(float v) {
    return v > 0.01f ? (v - 0.01f) : (v < -0.01f ? (v + 0.01f) : 0.0f);
}

template<int LAYER>
__global__ __launch_bounds__(384) void k_mlp(const float* __restrict__ w,
                                             const float* __restrict__ bias) {
    extern __shared__ float smem[];
    float* swr = smem;             // [96][96]  w real (k-major, n contiguous)
    float* swi = swr + 9216;       // [96][96]  w imag
    float* sxr = swi + 9216;       // [128][SXP] x real ([m][k])
    float* sxi = sxr + MT*SXP;     // [128][SXP] x imag
    float* sbr = sxi + MT*SXP;     // [96]
    float* sbi = sbr + 96;         // [96]

    const int tid  = threadIdx.x;
    const int nblk = blockIdx.y;
    const int p0   = blockIdx.x * MT;

    const float* inR  = (LAYER == 1) ? g_AR : g_BR;
    const float* inI  = (LAYER == 1) ? g_AI : g_BI;
    float*       outR = (LAYER == 1) ? g_BR : g_AR;
    float*       outI = (LAYER == 1) ? g_BI : g_AI;

    // weights: w[2][8][96][96] -> real at nblk*9216, imag at (8+nblk)*9216
    const float4* wrg = (const float4*)(w + nblk * 9216);
    const float4* wig = (const float4*)(w + (NB + nblk) * 9216);
    for (int idx = tid; idx < 2304; idx += 384) {
        ((float4*)swr)[idx] = wrg[idx];
        ((float4*)swi)[idx] = wig[idx];
    }
    if (tid < 96) {
        sbr[tid] = bias[nblk*96 + tid];
        sbi[tid] = bias[(NB + nblk)*96 + tid];
    }
    // x tile: rows p0..p0+127, cols nblk*96..+95 (k contiguous in global)
    for (int idx = tid; idx < MT*24; idx += 384) {
        int m = idx / 24, kq = idx % 24;
        int g = (p0 + m)*CC + nblk*96 + kq*4;
        float4 vR = *(const float4*)(inR + g);
        float4 vI = *(const float4*)(inI + g);
        *(float4*)(sxr + m*SXP + kq*4) = vR;
        *(float4*)(sxi + m*SXP + kq*4) = vI;
    }
    __syncthreads();

    const int nt = tid % 24;      // 24 n-groups of 4 outputs
    const int mt = tid / 24;      // 16 m-groups of 8 positions
    const int n0 = nt * 4;
    const int m0 = mt * 8;

    float accR[8][4], accI[8][4];
    #pragma unroll
    for (int i = 0; i < 8; i++)
        #pragma unroll
        for (int j = 0; j < 4; j++) { accR[i][j] = 0.0f; accI[i][j] = 0.0f; }

    #pragma unroll 2
    for (int k = 0; k < 96; k++) {
        float4 wr4 = *(const float4*)(swr + k*96 + n0);
        float4 wi4 = *(const float4*)(swi + k*96 + n0);
        #pragma unroll
        for (int i = 0; i < 8; i++) {
            float xr = sxr[(m0 + i)*SXP + k];
            float xi = sxi[(m0 + i)*SXP + k];
            accR[i][0] = fmaf(xr, wr4.x, accR[i][0]);
            accR[i][1] = fmaf(xr, wr4.y, accR[i][1]);
            accR[i][2] = fmaf(xr, wr4.z, accR[i][2]);
            accR[i][3] = fmaf(xr, wr4.w, accR[i][3]);
            accR[i][0] = fmaf(-xi, wi4.x, accR[i][0]);
            accR[i][1] = fmaf(-xi, wi4.y, accR[i][1]);
            accR[i][2] = fmaf(-xi, wi4.z, accR[i][2]);
            accR[i][3] = fmaf(-xi, wi4.w, accR[i][3]);
            accI[i][0] = fmaf(xi, wr4.x, accI[i][0]);
            accI[i][1] = fmaf(xi, wr4.y, accI[i][1]);
            accI[i][2] = fmaf(xi, wr4.z, accI[i][2]);
            accI[i][3] = fmaf(xi, wr4.w, accI[i][3]);
            accI[i][0] = fmaf(xr, wi4.x, accI[i][0]);
            accI[i][1] = fmaf(xr, wi4.y, accI[i][1]);
            accI[i][2] = fmaf(xr, wi4.z, accI[i][2]);
            accI[i][3] = fmaf(xr, wi4.w, accI[i][3]);
        }
    }

    // epilogue: bias + nonlinearity, float4 stores
    #pragma unroll
    for (int i = 0; i < 8; i++) {
        int p = p0 + m0 + i;
        float4 oR, oI;
        float r0 = accR[i][0] + sbr[n0+0], r1 = accR[i][1] + sbr[n0+1];
        float r2 = accR[i][2] + sbr[n0+2], r3 = accR[i][3] + sbr[n0+3];
        float s0 = accI[i][0] + sbi[n0+0], s1 = accI[i][1] + sbi[n0+1];
        float s2 = accI[i][2] + sbi[n0+2], s3 = accI[i][3] + sbi[n0+3];
        if (LAYER == 1) {
            oR.x = gelu_exact(r0); oR.y = gelu_exact(r1);
            oR.z = gelu_exact(r2); oR.w = gelu_exact(r3);
            oI.x = gelu_exact(s0); oI.y = gelu_exact(s1);
            oI.z = gelu_exact(s2); oI.w = gelu_exact(s3);
        } else {
            oR.x = sshrink(r0); oR.y = sshrink(r1);
            oR.z = sshrink(r2); oR.w = sshrink(r3);
            oI.x = sshrink(s0); oI.y = sshrink(s1);
            oI.z = sshrink(s2); oI.w = sshrink(s3);
        }
        int g = p*CC + nblk*96 + n0;
        *(float4*)(outR + g) = oR;
        *(float4*)(outI + g) = oI;
    }
}

// ---------------------------------------------------------------------------

extern "C" void kernel_launch(void* const* d_in, const int* in_sizes, int n_in,
                              void* d_out, int out_size) {
    const float* x  = (const float*)d_in[0];
    const float* w1 = (const float*)d_in[1];
    const float* b1 = (const float*)d_in[2];
    const float* w2 = (const float*)d_in[3];
    const float* b2 = (const float*)d_in[4];
    float* out = (float*)d_out;

    cudaFuncSetAttribute(k_mlp<1>, cudaFuncAttributeMaxDynamicSharedMemorySize, MLP_SMEM_BYTES);
    cudaFuncSetAttribute(k_mlp<2>, cudaFuncAttributeMaxDynamicSharedMemorySize, MLP_SMEM_BYTES);

    dim3 gfft(CC/32, HH, BB);   // (24,128,4)
    dim3 ghf (CC/32, WF, BB);   // (24, 65,4)
    dim3 gmlp(NPOS/MT, NB);     // (260,  8)

    k_wfft<<<gfft, 1024>>>(x);
    k_hfft<-1, true><<<ghf, 1024>>>();
    k_mlp<1><<<gmlp, 384, MLP_SMEM_BYTES>>>(w1, b1);
    k_mlp<2><<<gmlp, 384, MLP_SMEM_BYTES>>>(w2, b2);
    k_hfft<1, false><<<ghf, 1024>>>();
    k_iwfft<<<gfft, 1024>>>(out);
}

// round 14
// speedup vs baseline: 1.3224x; 1.3224x over previous
#include <cuda_runtime.h>
#include <math.h>

// AFNO2D: rfft2(ortho) -> blockwise complex MLP (GELU, softshrink) -> irfft2(ortho)
// x[4,128,128,768] fp32. Scratch in __device__ globals (no allocation).
//
// R10: fix inverse packed rFFT — zero Im at kw=0 and kw=64 before packing
// Z=A+iB (irfft discards Im(DC)/Im(Nyquist); post-MLP spectrum is NOT Hermitian).

#define BB 4
#define HH 128
#define WW 128
#define CC 768
#define NB 8
#define WF 65            // W half-spectrum size
#define NPOS (BB*WF*HH)  // 33280 frequency positions

// Spectrum scratch: [b][kw(0..64)][h or kh][c]
__device__ float g_AR[BB*WF*HH*CC];
__device__ float g_AI[BB*WF*HH*CC];

// ---------------------------------------------------------------------------
// Shared-memory cooperative 128-point complex FFT, 32 channel lanes.
// Layout: s[idx*32 + c]; warp = 32 consecutive c -> conflict-free.
// Three merged radix-2 stage-pairs (radix-4 groups) + one final radix-2 stage.
// ---------------------------------------------------------------------------

__device__ __forceinline__ void build_tw(float* twc, float* tws, int tid, float sign) {
    // index (half-1)+k, angle = sign * pi * k / half. 127 entries.
    if (tid < 127) {
        int half = 1 << (31 - __clz(tid + 1));
        int k = tid + 1 - half;
        float ang = sign * 3.14159265358979323846f * (float)k / (float)half;
        twc[tid] = cosf(ang);
        tws[tid] = sinf(ang);
    }
}

__device__ __forceinline__ void fft128_r4(float* sr, float* si,
                                          const float* twc, const float* tws, int tid) {
    const int c = tid & 31;
    const int g = tid >> 5;                // radix-4 group 0..31
    #pragma unroll
    for (int s = 0; s < 6; s += 2) {
        const int half = 1 << s;
        int k = g & (half - 1);
        int outer = g >> s;
        int i0 = (outer << (s + 2)) + k;
        int i1 = i0 + half, i2 = i0 + 2*half, i3 = i0 + 3*half;
        float tr  = twc[half-1+k],         ti  = tws[half-1+k];
        float u0r = twc[2*half-1+k],       u0i = tws[2*half-1+k];
        float u1r = twc[2*half-1+k+half],  u1i = tws[2*half-1+k+half];
        float a0r = sr[i0*32+c], a0i = si[i0*32+c];
        float a1r = sr[i1*32+c], a1i = si[i1*32+c];
        float a2r = sr[i2*32+c], a2i = si[i2*32+c];
        float a3r = sr[i3*32+c], a3i = si[i3*32+c];
        // stage s (twiddle t on both pairs)
        float br = a1r*tr - a1i*ti, bi = a1r*ti + a1i*tr;
        float A0r = a0r + br, A0i = a0i + bi;
        float A1r = a0r - br, A1i = a0i - bi;
        br = a3r*tr - a3i*ti;  bi = a3r*ti + a3i*tr;
        float A2r = a2r + br, A2i = a2i + bi;
        float A3r = a2r - br, A3i = a2i - bi;
        // stage s+1 (pairs (0,2) with u0, (1,3) with u1)
        float cr = A2r*u0r - A2i*u0i, ci2 = A2r*u0i + A2i*u0r;
        sr[i0*32+c] = A0r + cr;  si[i0*32+c] = A0i + ci2;
        sr[i2*32+c] = A0r - cr;  si[i2*32+c] = A0i - ci2;
        cr = A3r*u1r - A3i*u1i;  ci2 = A3r*u1i + A3i*u1r;
        sr[i1*32+c] = A1r + cr;  si[i1*32+c] = A1i + ci2;
        sr[i3*32+c] = A1r - cr;  si[i3*32+c] = A1i - ci2;
        __syncthreads();
    }
    // final radix-2 stage, half = 64
    #pragma unroll
    for (int q = 0; q < 2; q++) {
        int j = g + (q << 5);              // 0..63
        float twr = twc[63+j], twi = tws[63+j];
        int i0 = j, i1 = j + 64;
        float ar = sr[i1*32+c], ai = si[i1*32+c];
        float vr = ar*twr - ai*twi, vi = ar*twi + ai*twr;
        float ur = sr[i0*32+c], ui = si[i0*32+c];
        sr[i0*32+c] = ur + vr;  si[i0*32+c] = ui + vi;
        sr[i1*32+c] = ur - vr;  si[i1*32+c] = ui - vi;
    }
    __syncthreads();
}

// ---- Stage 1: real FFT along W, two real channels packed per complex lane --
// Block handles 64 real channels: pair (c0+c, c0+32+c) -> one complex FFT.
__global__ __launch_bounds__(1024) void k_wfft(const float* __restrict__ x) {
    __shared__ float sr[4096], si[4096], twc[128], tws[128];
    const int tid = threadIdx.x;
    const int c0  = blockIdx.x * 64;
    const int h   = blockIdx.y;
    const int b   = blockIdx.z;
    build_tw(twc, tws, tid, -1.0f);
    const float* src = x + ((b*HH + h)*WW)*CC + c0;
    for (int idx = tid; idx < 4096; idx += 1024) {
        int w = idx >> 5, c = idx & 31;
        int r = __brev(w) >> 25;
        sr[r*32 + c] = src[w*CC + c];          // channel a
        si[r*32 + c] = src[w*CC + 32 + c];     // channel b
    }
    __syncthreads();
    fft128_r4(sr, si, twc, tws, tid);
    // split: Xa[k] = (Z[k]+conj(Z[-k]))/2 ; Xb[k] = -i(Z[k]-conj(Z[-k]))/2
    float* dR = g_AR + ((b*WF)*HH + h)*CC + c0;
    float* dI = g_AI + ((b*WF)*HH + h)*CC + c0;
    for (int idx = tid; idx < 65*32; idx += 1024) {
        int k = idx >> 5, c = idx & 31;
        int m = (128 - k) & 127;
        float z1r = sr[k*32+c], z1i = si[k*32+c];
        float z2r = sr[m*32+c], z2i = si[m*32+c];
        int off = k*(HH*CC) + c;
        dR[off]      = 0.5f*(z1r + z2r);
        dI[off]      = 0.5f*(z1i - z2i);
        dR[off + 32] = 0.5f*(z1i + z2i);
        dI[off + 32] = 0.5f*(z2r - z1r);
    }
}

// ---- Complex FFT along H, in-place. SIGN=-1 fwd (ortho 1/128), +1 inverse --
template<int SIGN, bool SCALE>
__global__ __launch_bounds__(1024) void k_hfft() {
    __shared__ float sr[4096], si[4096], twc[128], tws[128];
    const int tid = threadIdx.x;
    const int c0  = blockIdx.x * 32;
    const int kw  = blockIdx.y;
    const int b   = blockIdx.z;
    build_tw(twc, tws, tid, (float)SIGN);
    float* pR = g_AR + ((b*WF + kw)*HH)*CC + c0;
    float* pI = g_AI + ((b*WF + kw)*HH)*CC + c0;
    for (int idx = tid; idx < 4096; idx += 1024) {
        int hh = idx >> 5, c = idx & 31;
        int r = __brev(hh) >> 25;
        sr[r*32 + c] = pR[hh*CC + c];
        si[r*32 + c] = pI[hh*CC + c];
    }
    __syncthreads();
    fft128_r4(sr, si, twc, tws, tid);
    const float sc = SCALE ? 0.0078125f : 1.0f;
    for (int idx = tid; idx < 4096; idx += 1024) {
        int kh = idx >> 5, c = idx & 31;
        pR[kh*CC + c] = sr[kh*32 + c] * sc;
        pI[kh*CC + c] = si[kh*32 + c] * sc;
    }
}

// ---- Final: inverse real FFT along W, packed pair -> 64 real channels -----
__global__ __launch_bounds__(1024) void k_iwfft(float* __restrict__ out) {
    __shared__ float sr[4096], si[4096], twc[128], tws[128];
    const int tid = threadIdx.x;
    const int c0  = blockIdx.x * 64;
    const int h   = blockIdx.y;
    const int b   = blockIdx.z;
    build_tw(twc, tws, tid, 1.0f);
    const float* pR = g_AR + ((b*WF)*HH + h)*CC + c0;
    const float* pI = g_AI + ((b*WF)*HH + h)*CC + c0;
    // Z[k] = A[k] + i*B[k], Hermitian-extended to k=65..127.
    // irfft convention: imaginary parts of DC (kw=0) and Nyquist (kw=64)
    // bins are discarded. Post-MLP spectrum is NOT Hermitian, so these are
    // nonzero and MUST be zeroed here or they cross-contaminate the packed
    // channel pair (R7 bug: rel_err 8.8e-2 from exactly these two bins).
    for (int idx = tid; idx < 4096; idx += 1024) {
        int kk = idx >> 5, c = idx & 31;
        int m = (kk <= 64) ? kk : (128 - kk);
        int off = m*(HH*CC) + c;
        float Ar = pR[off],      Ai = pI[off];
        float Br = pR[off + 32], Bi = pI[off + 32];
        if (m == 0 || m == 64) { Ai = 0.0f; Bi = 0.0f; }
        float zr, zi;
        if (kk <= 64) { zr = Ar - Bi;  zi = Ai + Br; }
        else          { zr = Ar + Bi;  zi = Br - Ai; }
        int r = __brev(kk) >> 25;
        sr[r*32 + c] = zr;
        si[r*32 + c] = zi;
    }
    __syncthreads();
    fft128_r4(sr, si, twc, tws, tid);
    float* dst = out + ((b*HH + h)*WW)*CC + c0;
    for (int idx = tid; idx < 4096; idx += 1024) {
        int w = idx >> 5, c = idx & 31;
        dst[w*CC + c]      = sr[w*32 + c] * 0.0078125f;   // channel a
        dst[w*CC + 32 + c] = si[w*32 + c] * 0.0078125f;   // channel b
    }
}

// ---------------------------------------------------------------------------
// Fused block-diagonal complex MLP: layer1 (GELU) + layer2 (softshrink).
// CTA = 128 positions x one channel block. o1 lives in smem between layers.
// smem operands interleaved (r,i): x via LDS.64, w via 2x LDS.128 per k.
// ---------------------------------------------------------------------------

#define MT 128
#define PX 192   // interleaved pitch (96 complex = 192 floats)
#define MLP_SMEM_FLOATS (96*PX + MT*PX + 4*96)
#define MLP_SMEM_BYTES  (MLP_SMEM_FLOATS * 4)

__device__ __forceinline__ float gelu_exact(float v) {
    return 0.5f * v * (1.0f + erff(v * 0.70710678118654752f));
}
__device__ __forceinline__ float sshrink(float v) {
    return v > 0.01f ? (v - 0.01f) : (v < -0.01f ? (v + 0.01f) : 0.0f);
}

__device__ __forceinline__ void load_w_interleaved(float* sw, const float* w,
                                                   int nblk, int tid) {
    const float4* wrg = (const float4*)(w + nblk * 9216);
    const float4* wig = (const float4*)(w + (NB + nblk) * 9216);
    for (int idx = tid; idx < 2304; idx += 384) {
        float4 r = wrg[idx], im = wig[idx];
        float* p = sw + (idx / 24) * PX + (idx % 24) * 8;
        ((float2*)p)[0] = make_float2(r.x, im.x);
        ((float2*)p)[1] = make_float2(r.y, im.y);
        ((float2*)p)[2] = make_float2(r.z, im.z);
        ((float2*)p)[3] = make_float2(r.w, im.w);
    }
}

__device__ __forceinline__ void mlp_gemm(const float* __restrict__ sw,
                                         const float* __restrict__ sx,
                                         int m0, int n0,
                                         float accR[8][4], float accI[8][4]) {
    #pragma unroll 4
    for (int k = 0; k < 96; k++) {
        float4 wA = *(const float4*)(sw + k*PX + n0*2);      // (wr0,wi0,wr1,wi1)
        float4 wB = *(const float4*)(sw + k*PX + n0*2 + 4);  // (wr2,wi2,wr3,wi3)
        #pragma unroll
        for (int i = 0; i < 8; i++) {
            float2 xv = *(const float2*)(sx + (m0 + i)*PX + 2*k);
            accR[i][0] = fmaf(xv.x, wA.x, accR[i][0]);
            accR[i][0] = fmaf(-xv.y, wA.y, accR[i][0]);
            accI[i][0] = fmaf(xv.y, wA.x, accI[i][0]);
            accI[i][0] = fmaf(xv.x, wA.y, accI[i][0]);
            accR[i][1] = fmaf(xv.x, wA.z, accR[i][1]);
            accR[i][1] = fmaf(-xv.y, wA.w, accR[i][1]);
            accI[i][1] = fmaf(xv.y, wA.z, accI[i][1]);
            accI[i][1] = fmaf(xv.x, wA.w, accI[i][1]);
            accR[i][2] = fmaf(xv.x, wB.x, accR[i][2]);
            accR[i][2] = fmaf(-xv.y, wB.y, accR[i][2]);
            accI[i][2] = fmaf(xv.y, wB.x, accI[i][2]);
            accI[i][2] = fmaf(xv.x, wB.y, accI[i][2]);
            accR[i][3] = fmaf(xv.x, wB.z, accR[i][3]);
            accR[i][3] = fmaf(-xv.y, wB.w, accR[i][3]);
            accI[i][3] = fmaf(xv.y, wB.z, accI[i][3]);
            accI[i][3] = fmaf(xv.x, wB.w, accI[i][3]);
        }
    }
}

__global__ __launch_bounds__(384) void k_mlp_fused(const float* __restrict__ w1,
                                                   const float* __restrict__ b1,
                                                   const float* __restrict__ w2,
                                                   const float* __restrict__ b2) {
    extern __shared__ float smem[];
    float* sw   = smem;              // [96][96] complex interleaved
    float* sx   = sw + 96*PX;        // [128][96] complex interleaved
    float* sb1r = sx + MT*PX;
    float* sb1i = sb1r + 96;
    float* sb2r = sb1i + 96;
    float* sb2i = sb2r + 96;

    const int tid  = threadIdx.x;
    const int nblk = blockIdx.y;
    const int p0   = blockIdx.x * MT;

    load_w_interleaved(sw, w1, nblk, tid);
    if (tid < 96) {
        sb1r[tid] = b1[nblk*96 + tid];
        sb1i[tid] = b1[(NB + nblk)*96 + tid];
        sb2r[tid] = b2[nblk*96 + tid];
        sb2i[tid] = b2[(NB + nblk)*96 + tid];
    }
    for (int idx = tid; idx < MT*24; idx += 384) {
        int m = idx / 24, kq = (idx % 24) * 4;
        int g = (p0 + m)*CC + nblk*96 + kq;
        float4 vR = *(const float4*)(g_AR + g);
        float4 vI = *(const float4*)(g_AI + g);
        float* p = sx + m*PX + kq*2;
        ((float2*)p)[0] = make_float2(vR.x, vI.x);
        ((float2*)p)[1] = make_float2(vR.y, vI.y);
        ((float2*)p)[2] = make_float2(vR.z, vI.z);
        ((float2*)p)[3] = make_float2(vR.w, vI.w);
    }
    __syncthreads();

    const int n0 = (tid % 24) * 4;
    const int m0 = (tid / 24) * 8;

    float accR[8][4], accI[8][4];
    #pragma unroll
    for (int i = 0; i < 8; i++)
        #pragma unroll
        for (int j = 0; j < 4; j++) { accR[i][j] = 0.0f; accI[i][j] = 0.0f; }

    // ---- layer 1 ----
    mlp_gemm(sw, sx, m0, n0, accR, accI);
    __syncthreads();                 // all phase-1 reads of sx/sw complete

    // o1 = GELU(acc + b1) -> overwrite sx ; reload weights with w2
    #pragma unroll
    for (int i = 0; i < 8; i++) {
        float* p = sx + (m0 + i)*PX + n0*2;
        #pragma unroll
        for (int j = 0; j < 4; j++) {
            float r = gelu_exact(accR[i][j] + sb1r[n0 + j]);
            float s = gelu_exact(accI[i][j] + sb1i[n0 + j]);
            ((float2*)p)[j] = make_float2(r, s);
        }
    }
    load_w_interleaved(sw, w2, nblk, tid);
    __syncthreads();

    #pragma unroll
    for (int i = 0; i < 8; i++)
        #pragma unroll
        for (int j = 0; j < 4; j++) { accR[i][j] = 0.0f; accI[i][j] = 0.0f; }

    // ---- layer 2 ----
    mlp_gemm(sw, sx, m0, n0, accR, accI);

    // epilogue: bias + softshrink -> g_A (in place)
    #pragma unroll
    for (int i = 0; i < 8; i++) {
        int g = (p0 + m0 + i)*CC + nblk*96 + n0;
        float4 oR, oI;
        oR.x = sshrink(accR[i][0] + sb2r[n0+0]);
        oR.y = sshrink(accR[i][1] + sb2r[n0+1]);
        oR.z = sshrink(accR[i][2] + sb2r[n0+2]);
        oR.w = sshrink(accR[i][3] + sb2r[n0+3]);
        oI.x = sshrink(accI[i][0] + sb2i[n0+0]);
        oI.y = sshrink(accI[i][1] + sb2i[n0+1]);
        oI.z = sshrink(accI[i][2] + sb2i[n0+2]);
        oI.w = sshrink(accI[i][3] + sb2i[n0+3]);
        *(float4*)(g_AR + g) = oR;
        *(float4*)(g_AI + g) = oI;
    }
}

// ---------------------------------------------------------------------------

extern "C" void kernel_launch(void* const* d_in, const int* in_sizes, int n_in,
                              void* d_out, int out_size) {
    const float* x  = (const float*)d_in[0];
    const float* w1 = (const float*)d_in[1];
    const float* b1 = (const float*)d_in[2];
    const float* w2 = (const float*)d_in[3];
    const float* b2 = (const float*)d_in[4];
    float* out = (float*)d_out;

    cudaFuncSetAttribute(k_mlp_fused, cudaFuncAttributeMaxDynamicSharedMemorySize,
                         MLP_SMEM_BYTES);

    dim3 gfftw(CC/64, HH, BB);   // (12,128,4)  packed W kernels
    dim3 ghf  (CC/32, WF, BB);   // (24, 65,4)
    dim3 gmlp (NPOS/MT, NB);     // (260,  8)

    k_wfft<<<gfftw, 1024>>>(x);
    k_hfft<-1, true><<<ghf, 1024>>>();
    k_mlp_fused<<<gmlp, 384, MLP_SMEM_BYTES>>>(w1, b1, w2, b2);
    k_hfft<1, false><<<ghf, 1024>>>();
    k_iwfft<<<gfftw, 1024>>>(out);
}